// round 14
// baseline (speedup 1.0000x reference)
#include <cuda_runtime.h>
#include <cuda_fp16.h>
#include <cstdint>

// ---------------------------------------------------------------------------
// SNN on B200 (compute_100 => mma.sync m16n8k16 FP16, 3-term split,
//              planar planes (W1 x32), ldmatrix feeds, 3-stage cp.async ring,
//              term-outermost MMA order, drain every 2 K-tiles)
// ---------------------------------------------------------------------------

#define BATCH   256
#define T_STEPS 128
#define K_IN    1156
#define N_HID   1024
#define N_OUT   10
#define M_TOTAL (BATCH * T_STEPS)   // 32768
#define KTILES  19                  // ceil(1156/64)
#define K_PAD   (KTILES * 64)       // 1216
#define SROW_W  36                  // SMEM row stride in b32 words
#define PLANE_W (128 * SROW_W)      // 4608 words per plane per stage
#define W_SCALE 32.0f
#define W_INV   0.03125f

__device__ __half   g_xs[(size_t)2 * M_TOTAL * K_PAD];   // hi plane, lo plane
__device__ __half   g_ws[(size_t)2 * N_HID  * K_PAD];    // scaled by 32
__device__ uint32_t g_spkbits[(size_t)M_TOTAL * 32];     // 4 MB
__device__ float    g_cur2[(size_t)M_TOTAL * N_OUT];     // 1.3 MB

// ===================== helpers =============================================
__device__ __forceinline__ uint32_t smem_u32(const void* p) {
    uint32_t a;
    asm("{ .reg .u64 t; cvta.to.shared.u64 t, %1; cvt.u32.u64 %0, t; }"
        : "=r"(a) : "l"(p));
    return a;
}
__device__ __forceinline__ void cp_async16(uint32_t dst, const void* src) {
    asm volatile("cp.async.cg.shared.global [%0], [%1], 16;"
                 :: "r"(dst), "l"(src));
}
#define CP_COMMIT() asm volatile("cp.async.commit_group;" ::: "memory")
#define CP_WAIT1()  asm volatile("cp.async.wait_group 1;" ::: "memory")

__device__ __forceinline__ void ldsm_x4(uint32_t& r0, uint32_t& r1,
                                        uint32_t& r2, uint32_t& r3, uint32_t addr) {
    asm volatile("ldmatrix.sync.aligned.m8n8.x4.shared.b16 {%0,%1,%2,%3}, [%4];"
                 : "=r"(r0), "=r"(r1), "=r"(r2), "=r"(r3) : "r"(addr));
}

__device__ __forceinline__ void mma16(float* c, const uint32_t* a, const uint32_t* b) {
    asm volatile(
        "mma.sync.aligned.m16n8k16.row.col.f32.f16.f16.f32 "
        "{%0,%1,%2,%3}, {%4,%5,%6,%7}, {%8,%9}, {%0,%1,%2,%3};"
        : "+f"(c[0]), "+f"(c[1]), "+f"(c[2]), "+f"(c[3])
        : "r"(a[0]), "r"(a[1]), "r"(a[2]), "r"(a[3]), "r"(b[0]), "r"(b[1]));
}

// ===================== P: fp16 planar split prepass ========================
__global__ __launch_bounds__(256)
void split_prepass(const float* __restrict__ src, __half* __restrict__ dst_hi,
                   __half* __restrict__ dst_lo, int rows, float scale)
{
    const size_t idx = (size_t)blockIdx.x * 256 + threadIdx.x;  // 4-elem chunk
    const size_t nchunk = (size_t)rows * (K_PAD / 4);
    if (idx >= nchunk) return;
    const int row = (int)(idx / (K_PAD / 4));
    const int k0  = (int)(idx % (K_PAD / 4)) * 4;

    float4 v = make_float4(0.f, 0.f, 0.f, 0.f);
    if (k0 < K_IN) {   // K_IN % 4 == 0
        v = *(const float4*)(src + (size_t)row * K_IN + k0);
        v.x *= scale; v.y *= scale; v.z *= scale; v.w *= scale;
    }

    __half hx = __float2half_rn(v.x), hy = __float2half_rn(v.y);
    __half hz = __float2half_rn(v.z), hw = __float2half_rn(v.w);
    __half lx = __float2half_rn(v.x - __half2float(hx));
    __half ly = __float2half_rn(v.y - __half2float(hy));
    __half lz = __float2half_rn(v.z - __half2float(hz));
    __half lw = __float2half_rn(v.w - __half2float(hw));

    const size_t o = (size_t)row * K_PAD + k0;
    uint2 ph, pl;
    ph.x = (uint32_t)__half_as_ushort(hx) | ((uint32_t)__half_as_ushort(hy) << 16);
    ph.y = (uint32_t)__half_as_ushort(hz) | ((uint32_t)__half_as_ushort(hw) << 16);
    pl.x = (uint32_t)__half_as_ushort(lx) | ((uint32_t)__half_as_ushort(ly) << 16);
    pl.y = (uint32_t)__half_as_ushort(lz) | ((uint32_t)__half_as_ushort(lw) << 16);
    *(uint2*)(dst_hi + o) = ph;
    *(uint2*)(dst_lo + o) = pl;
}

// ===================== K1: GEMM + fused spike scan =========================
#define STAGE_W   (4 * PLANE_W)              // 18432 words = 73728 B
#define NSTAGE    3
#define GEMM_SMEM (NSTAGE * STAGE_W * 4)     // 221184 B

__global__ __launch_bounds__(256, 1)
void snn_gemm_spike()
{
    extern __shared__ uint32_t sm[];
    const uint32_t sbase = smem_u32(sm);
    const int tid  = threadIdx.x;          // 256 threads, 8 warps
    const int wid  = tid >> 5;
    const int lane = tid & 31;
    const int wm   = wid >> 2;             // 0..1 -> 64 rows
    const int wn   = wid & 3;              // 0..3 -> 32 cols
    const int b    = blockIdx.y;
    const int n0   = blockIdx.x * 128;

    const __half* xs_hi = g_xs;
    const __half* xs_lo = g_xs + (size_t)M_TOTAL * K_PAD;
    const __half* ws_hi = g_ws;
    const __half* ws_lo = g_ws + (size_t)N_HID * K_PAD;

    const size_t arow0 = (size_t)b * 128 * K_PAD;
    const size_t brow0 = (size_t)n0 * K_PAD;

    // ldmatrix per-lane byte offsets (within a plane)
    const int a_row = wm * 64 + (lane & 7) + ((lane >> 3) & 1) * 8;
    const uint32_t aoff = (uint32_t)(a_row * SROW_W + ((lane >> 4) & 1) * 4) * 4;
    const int b_row = wn * 32 + (lane & 7) + ((lane >> 4) & 1) * 8;
    const uint32_t boff = (uint32_t)(b_row * SROW_W + ((lane >> 3) & 1) * 4) * 4;

    float sum[4][4][4];
    float acc[4][4][4];
#pragma unroll
    for (int i = 0; i < 4; i++)
#pragma unroll
        for (int j = 0; j < 4; j++)
#pragma unroll
            for (int q = 0; q < 4; q++) sum[i][j][q] = 0.f;

    auto prefetch = [&](int it) {
        const int s  = it % NSTAGE;
        const int kb = it * 64;
        const uint32_t sst = sbase + (uint32_t)s * STAGE_W * 4;
#pragma unroll
        for (int q = 0; q < 16; ++q) {
            const int plane = q >> 2;
            const int f     = (q & 3) * 256 + tid;
            const int row   = f >> 3;
            const int j     = f & 7;
            const uint32_t soff = (uint32_t)(plane * PLANE_W + row * SROW_W + j * 4) * 4;
            const __half* src;
            if (plane == 0)      src = xs_hi + arow0 + (size_t)row * K_PAD + kb + j * 8;
            else if (plane == 1) src = xs_lo + arow0 + (size_t)row * K_PAD + kb + j * 8;
            else if (plane == 2) src = ws_hi + brow0 + (size_t)row * K_PAD + kb + j * 8;
            else                 src = ws_lo + brow0 + (size_t)row * K_PAD + kb + j * 8;
            cp_async16(sst + soff, src);
        }
    };

    prefetch(0); CP_COMMIT();
    prefetch(1); CP_COMMIT();

    const int g  = lane >> 2;   // epilogue C layout
    const int tg = lane & 3;

    for (int it = 0; it < KTILES; ++it) {
        CP_WAIT1();             // tile it resident (it+1 may be in flight)
        __syncthreads();        // all threads' copies of tile it visible
        if (it + 2 < KTILES) prefetch(it + 2);   // writes stage consumed at it-1
        CP_COMMIT();

        const uint32_t stg = sbase + (uint32_t)(it % NSTAGE) * STAGE_W * 4;
        const uint32_t aAh = stg + aoff;
        const uint32_t aAl = aAh + PLANE_W * 4;
        const uint32_t bBh = stg + 2 * PLANE_W * 4 + boff;
        const uint32_t bBl = bBh + PLANE_W * 4;

        if ((it & 1) == 0) {    // fresh TC accumulator every 2 K-tiles (K=128)
#pragma unroll
            for (int i = 0; i < 4; i++)
#pragma unroll
                for (int j = 0; j < 4; j++)
#pragma unroll
                    for (int q = 0; q < 4; q++) acc[i][j][q] = 0.f;
        }

#pragma unroll
        for (int ks = 0; ks < 4; ++ks) {
            uint32_t ahi[4][4], alo[4][4], bhi[4][2], blo[4][2];
            const uint32_t kso = (uint32_t)ks * 32;   // ks*8 words * 4B
#pragma unroll
            for (int mi = 0; mi < 4; ++mi) {
                const uint32_t d = kso + (uint32_t)mi * (16 * SROW_W * 4);
                ldsm_x4(ahi[mi][0], ahi[mi][1], ahi[mi][2], ahi[mi][3], aAh + d);
                ldsm_x4(alo[mi][0], alo[mi][1], alo[mi][2], alo[mi][3], aAl + d);
            }
#pragma unroll
            for (int np = 0; np < 2; ++np) {
                const uint32_t d = kso + (uint32_t)np * (16 * SROW_W * 4);
                ldsm_x4(bhi[2*np][0], bhi[2*np][1], bhi[2*np+1][0], bhi[2*np+1][1], bBh + d);
                ldsm_x4(blo[2*np][0], blo[2*np][1], blo[2*np+1][0], blo[2*np+1][1], bBl + d);
            }
            // term-outermost: consecutive MMAs hit different accumulators
#pragma unroll
            for (int mi = 0; mi < 4; ++mi)
#pragma unroll
                for (int ni = 0; ni < 4; ++ni)
                    mma16(acc[mi][ni], ahi[mi], bhi[ni]);
#pragma unroll
            for (int mi = 0; mi < 4; ++mi)
#pragma unroll
                for (int ni = 0; ni < 4; ++ni)
                    mma16(acc[mi][ni], ahi[mi], blo[ni]);
#pragma unroll
            for (int mi = 0; mi < 4; ++mi)
#pragma unroll
                for (int ni = 0; ni < 4; ++ni)
                    mma16(acc[mi][ni], alo[mi], bhi[ni]);
        }

        if ((it & 1) == 1 || it == KTILES - 1) {   // drain every 2 tiles
#pragma unroll
            for (int mi = 0; mi < 4; ++mi)
#pragma unroll
                for (int ni = 0; ni < 4; ++ni)
#pragma unroll
                    for (int q = 0; q < 4; ++q)
                        sum[mi][ni][q] += acc[mi][ni][q];
        }
    }
    __syncthreads();   // all MMAs done before stage SMEM is reused for cur

    // ---- epilogue: descale -> SMEM cur tile [128 t][132], LIF + ballot ----
    float* cur = (float*)sm;
#pragma unroll
    for (int mi = 0; mi < 4; ++mi)
#pragma unroll
        for (int ni = 0; ni < 4; ++ni) {
            const int r = wm * 64 + mi * 16 + g;
            const int c = wn * 32 + ni * 8 + tg * 2;
            cur[r * 132 + c]           = sum[mi][ni][0] * W_INV;
            cur[r * 132 + c + 1]       = sum[mi][ni][1] * W_INV;
            cur[(r + 8) * 132 + c]     = sum[mi][ni][2] * W_INV;
            cur[(r + 8) * 132 + c + 1] = sum[mi][ni][3] * W_INV;
        }
    __syncthreads();

    if (tid < 128) {
        float mem1 = 0.f;
        uint32_t* dst = g_spkbits + (size_t)b * 128 * 32 + blockIdx.x * 4 + wid;
        float c = cur[tid];
#pragma unroll 4
        for (int t = 0; t < T_STEPS; ++t) {
            float cn = (t + 1 < T_STEPS) ? cur[(t + 1) * 132 + tid] : 0.f;
            const float reset = (mem1 > 1.0f) ? 1.0f : 0.0f;
            mem1 = 0.95f * mem1 + c - reset;
            const uint32_t word = __ballot_sync(0xffffffffu, mem1 > 1.0f);
            if (lane == 0) dst[(size_t)t * 32] = word;
            c = cn;
        }
    }
}

// ===================== K2: cur2 = spk @ W2^T from bitmask ==================
__global__ __launch_bounds__(256)
void snn_gemm2(const float* __restrict__ W2)   // [N_OUT, N_HID]
{
    __shared__ float w2s[N_HID * 11 + 32];
    const int tid  = threadIdx.x;
    const int wid  = tid >> 5;
    const int lane = tid & 31;

    for (int i = tid; i < N_HID * N_OUT; i += 256) {
        const int h = i / N_OUT;
        const int o = i - h * N_OUT;
        w2s[h * 11 + (h >> 5) + o] = W2[o * N_HID + h];
    }
    __syncthreads();

    const size_t m = (size_t)blockIdx.x * 8 + wid;
    uint32_t word = g_spkbits[m * 32 + lane];
    const int lbase = lane * 353;

    float acc[N_OUT];
#pragma unroll
    for (int o = 0; o < N_OUT; o++) acc[o] = 0.f;

    while (word) {
        const int bit = __ffs(word) - 1;
        word &= word - 1;
        const float* w = w2s + lbase + bit * 11;
#pragma unroll
        for (int o = 0; o < N_OUT; o++) acc[o] += w[o];
    }

#pragma unroll
    for (int o = 0; o < N_OUT; o++) {
        acc[o] += __shfl_down_sync(0xffffffffu, acc[o], 16);
        acc[o] += __shfl_down_sync(0xffffffffu, acc[o], 8);
        acc[o] += __shfl_down_sync(0xffffffffu, acc[o], 4);
        acc[o] += __shfl_down_sync(0xffffffffu, acc[o], 2);
        acc[o] += __shfl_down_sync(0xffffffffu, acc[o], 1);
    }
    if (lane == 0) {
#pragma unroll
        for (int o = 0; o < N_OUT; o++) g_cur2[m * N_OUT + o] = acc[o];
    }
}

// ===================== K3: mem2 leaky integration ==========================
__global__ void snn_scan2(float* __restrict__ out)   // [T, B, N_OUT]
{
    const int id = blockIdx.x * 256 + threadIdx.x;
    if (id >= BATCH * N_OUT) return;
    const int bb = id / N_OUT;
    const int o  = id - bb * N_OUT;

    float m2 = 0.f;
    for (int t = 0; t < T_STEPS; ++t) {
        m2 = 0.95f * m2 + g_cur2[((size_t)bb * T_STEPS + t) * N_OUT + o];
        out[((size_t)t * BATCH + bb) * N_OUT + o] = m2;
    }
}

// ===================== launch ==============================================
extern "C" void kernel_launch(void* const* d_in, const int* in_sizes, int n_in,
                              void* d_out, int out_size)
{
    const float* x  = (const float*)d_in[0];
    const float* W1 = (const float*)d_in[1];
    const float* W2 = (const float*)d_in[2];
    float* out = (float*)d_out;

    cudaFuncSetAttribute(snn_gemm_spike,
                         cudaFuncAttributeMaxDynamicSharedMemorySize, GEMM_SMEM);

    __half* xs; __half* ws;
    cudaGetSymbolAddress((void**)&xs, g_xs);
    cudaGetSymbolAddress((void**)&ws, g_ws);

    {   // fp16 planar split prepass (W1 scaled by 32)
        const size_t nx = (size_t)M_TOTAL * (K_PAD / 4);
        const size_t nw = (size_t)N_HID * (K_PAD / 4);
        split_prepass<<<(unsigned)((nx + 255) / 256), 256>>>(
            x, xs, xs + (size_t)M_TOTAL * K_PAD, M_TOTAL, 1.0f);
        split_prepass<<<(unsigned)((nw + 255) / 256), 256>>>(
            W1, ws, ws + (size_t)N_HID * K_PAD, N_HID, W_SCALE);
    }

    dim3 grid1(N_HID / 128, M_TOTAL / 128);    // (8, 256)
    snn_gemm_spike<<<grid1, 256, GEMM_SMEM>>>();
    snn_gemm2<<<M_TOTAL / 8, 256>>>(W2);
    snn_scan2<<<(BATCH * N_OUT + 255) / 256, 256>>>(out);
}

// round 15
// speedup vs baseline: 1.0634x; 1.0634x over previous
#include <cuda_runtime.h>
#include <cuda_fp16.h>
#include <cstdint>

// ---------------------------------------------------------------------------
// SNN on B200 (compute_100 => mma.sync m16n8k16 FP16, 3-term split,
//              planar planes (W1 x32), ldmatrix feeds, 2-stage ring [R13],
//              K2 with 32 rows/CTA to amortize the W2 SMEM fill)
// ---------------------------------------------------------------------------

#define BATCH   256
#define T_STEPS 128
#define K_IN    1156
#define N_HID   1024
#define N_OUT   10
#define M_TOTAL (BATCH * T_STEPS)   // 32768
#define KTILES  19                  // ceil(1156/64)
#define K_PAD   (KTILES * 64)       // 1216
#define SROW_W  36                  // SMEM row stride in b32 words
#define PLANE_W (128 * SROW_W)      // 4608 words per plane per stage
#define W_SCALE 32.0f
#define W_INV   0.03125f

__device__ __half   g_xs[(size_t)2 * M_TOTAL * K_PAD];   // hi plane, lo plane
__device__ __half   g_ws[(size_t)2 * N_HID  * K_PAD];    // scaled by 32
__device__ uint32_t g_spkbits[(size_t)M_TOTAL * 32];     // 4 MB
__device__ float    g_cur2[(size_t)M_TOTAL * N_OUT];     // 1.3 MB

// ===================== helpers =============================================
__device__ __forceinline__ uint32_t smem_u32(const void* p) {
    uint32_t a;
    asm("{ .reg .u64 t; cvta.to.shared.u64 t, %1; cvt.u32.u64 %0, t; }"
        : "=r"(a) : "l"(p));
    return a;
}
__device__ __forceinline__ void cp_async16(uint32_t dst, const void* src) {
    asm volatile("cp.async.cg.shared.global [%0], [%1], 16;"
                 :: "r"(dst), "l"(src));
}
#define CP_COMMIT() asm volatile("cp.async.commit_group;" ::: "memory")
#define CP_WAIT1()  asm volatile("cp.async.wait_group 1;" ::: "memory")

__device__ __forceinline__ void ldsm_x4(uint32_t& r0, uint32_t& r1,
                                        uint32_t& r2, uint32_t& r3, uint32_t addr) {
    asm volatile("ldmatrix.sync.aligned.m8n8.x4.shared.b16 {%0,%1,%2,%3}, [%4];"
                 : "=r"(r0), "=r"(r1), "=r"(r2), "=r"(r3) : "r"(addr));
}

__device__ __forceinline__ void mma16(float* c, const uint32_t* a, const uint32_t* b) {
    asm volatile(
        "mma.sync.aligned.m16n8k16.row.col.f32.f16.f16.f32 "
        "{%0,%1,%2,%3}, {%4,%5,%6,%7}, {%8,%9}, {%0,%1,%2,%3};"
        : "+f"(c[0]), "+f"(c[1]), "+f"(c[2]), "+f"(c[3])
        : "r"(a[0]), "r"(a[1]), "r"(a[2]), "r"(a[3]), "r"(b[0]), "r"(b[1]));
}

// ===================== P: fp16 planar split prepass ========================
__global__ __launch_bounds__(256)
void split_prepass(const float* __restrict__ src, __half* __restrict__ dst_hi,
                   __half* __restrict__ dst_lo, int rows, float scale)
{
    const size_t idx = (size_t)blockIdx.x * 256 + threadIdx.x;  // 4-elem chunk
    const size_t nchunk = (size_t)rows * (K_PAD / 4);
    if (idx >= nchunk) return;
    const int row = (int)(idx / (K_PAD / 4));
    const int k0  = (int)(idx % (K_PAD / 4)) * 4;

    float4 v = make_float4(0.f, 0.f, 0.f, 0.f);
    if (k0 < K_IN) {   // K_IN % 4 == 0
        v = *(const float4*)(src + (size_t)row * K_IN + k0);
        v.x *= scale; v.y *= scale; v.z *= scale; v.w *= scale;
    }

    __half hx = __float2half_rn(v.x), hy = __float2half_rn(v.y);
    __half hz = __float2half_rn(v.z), hw = __float2half_rn(v.w);
    __half lx = __float2half_rn(v.x - __half2float(hx));
    __half ly = __float2half_rn(v.y - __half2float(hy));
    __half lz = __float2half_rn(v.z - __half2float(hz));
    __half lw = __float2half_rn(v.w - __half2float(hw));

    const size_t o = (size_t)row * K_PAD + k0;
    uint2 ph, pl;
    ph.x = (uint32_t)__half_as_ushort(hx) | ((uint32_t)__half_as_ushort(hy) << 16);
    ph.y = (uint32_t)__half_as_ushort(hz) | ((uint32_t)__half_as_ushort(hw) << 16);
    pl.x = (uint32_t)__half_as_ushort(lx) | ((uint32_t)__half_as_ushort(ly) << 16);
    pl.y = (uint32_t)__half_as_ushort(lz) | ((uint32_t)__half_as_ushort(lw) << 16);
    *(uint2*)(dst_hi + o) = ph;
    *(uint2*)(dst_lo + o) = pl;
}

// ===================== K1: GEMM + fused spike scan (R13 config) ============
#define STAGE_W   (4 * PLANE_W)              // 18432 words
#define GEMM_SMEM (2 * STAGE_W * 4)          // 147456 B

__global__ __launch_bounds__(256, 1)
void snn_gemm_spike()
{
    extern __shared__ uint32_t sm[];
    const uint32_t sbase = smem_u32(sm);
    const int tid  = threadIdx.x;          // 256 threads, 8 warps
    const int wid  = tid >> 5;
    const int lane = tid & 31;
    const int wm   = wid >> 2;             // 0..1 -> 64 rows
    const int wn   = wid & 3;              // 0..3 -> 32 cols
    const int b    = blockIdx.y;
    const int n0   = blockIdx.x * 128;

    const __half* xs_hi = g_xs;
    const __half* xs_lo = g_xs + (size_t)M_TOTAL * K_PAD;
    const __half* ws_hi = g_ws;
    const __half* ws_lo = g_ws + (size_t)N_HID * K_PAD;

    const size_t arow0 = (size_t)b * 128 * K_PAD;
    const size_t brow0 = (size_t)n0 * K_PAD;

    const int a_row = wm * 64 + (lane & 7) + ((lane >> 3) & 1) * 8;
    const uint32_t aoff = (uint32_t)(a_row * SROW_W + ((lane >> 4) & 1) * 4) * 4;
    const int b_row = wn * 32 + (lane & 7) + ((lane >> 4) & 1) * 8;
    const uint32_t boff = (uint32_t)(b_row * SROW_W + ((lane >> 3) & 1) * 4) * 4;

    float sum[4][4][4];
#pragma unroll
    for (int i = 0; i < 4; i++)
#pragma unroll
        for (int j = 0; j < 4; j++)
#pragma unroll
            for (int q = 0; q < 4; q++) sum[i][j][q] = 0.f;

    auto prefetch = [&](int it) {
        const int s  = it & 1;
        const int kb = it * 64;
        const uint32_t sst = sbase + (uint32_t)s * STAGE_W * 4;
#pragma unroll
        for (int q = 0; q < 16; ++q) {
            const int plane = q >> 2;
            const int f     = (q & 3) * 256 + tid;
            const int row   = f >> 3;
            const int j     = f & 7;
            const uint32_t soff = (uint32_t)(plane * PLANE_W + row * SROW_W + j * 4) * 4;
            const __half* src;
            if (plane == 0)      src = xs_hi + arow0 + (size_t)row * K_PAD + kb + j * 8;
            else if (plane == 1) src = xs_lo + arow0 + (size_t)row * K_PAD + kb + j * 8;
            else if (plane == 2) src = ws_hi + brow0 + (size_t)row * K_PAD + kb + j * 8;
            else                 src = ws_lo + brow0 + (size_t)row * K_PAD + kb + j * 8;
            cp_async16(sst + soff, src);
        }
    };

    prefetch(0);
    CP_COMMIT();

    const int g  = lane >> 2;
    const int tg = lane & 3;

    for (int it = 0; it < KTILES; ++it) {
        if (it + 1 < KTILES) prefetch(it + 1);
        CP_COMMIT();
        CP_WAIT1();
        __syncthreads();

        const uint32_t stg = sbase + (uint32_t)(it & 1) * STAGE_W * 4;
        const uint32_t aAh = stg + aoff;
        const uint32_t aAl = aAh + PLANE_W * 4;
        const uint32_t bBh = stg + 2 * PLANE_W * 4 + boff;
        const uint32_t bBl = bBh + PLANE_W * 4;

        float acc[4][4][4];
#pragma unroll
        for (int i = 0; i < 4; i++)
#pragma unroll
            for (int j = 0; j < 4; j++)
#pragma unroll
                for (int q = 0; q < 4; q++) acc[i][j][q] = 0.f;

#pragma unroll
        for (int ks = 0; ks < 4; ++ks) {
            uint32_t ahi[4][4], alo[4][4], bhi[4][2], blo[4][2];
            const uint32_t kso = (uint32_t)ks * 32;
#pragma unroll
            for (int mi = 0; mi < 4; ++mi) {
                const uint32_t d = kso + (uint32_t)mi * (16 * SROW_W * 4);
                ldsm_x4(ahi[mi][0], ahi[mi][1], ahi[mi][2], ahi[mi][3], aAh + d);
                ldsm_x4(alo[mi][0], alo[mi][1], alo[mi][2], alo[mi][3], aAl + d);
            }
#pragma unroll
            for (int np = 0; np < 2; ++np) {
                const uint32_t d = kso + (uint32_t)np * (16 * SROW_W * 4);
                ldsm_x4(bhi[2*np][0], bhi[2*np][1], bhi[2*np+1][0], bhi[2*np+1][1], bBh + d);
                ldsm_x4(blo[2*np][0], blo[2*np][1], blo[2*np+1][0], blo[2*np+1][1], bBl + d);
            }
#pragma unroll
            for (int mi = 0; mi < 4; ++mi)
#pragma unroll
                for (int ni = 0; ni < 4; ++ni) {
                    mma16(acc[mi][ni], ahi[mi], bhi[ni]);
                    mma16(acc[mi][ni], ahi[mi], blo[ni]);
                    mma16(acc[mi][ni], alo[mi], bhi[ni]);
                }
        }

#pragma unroll
        for (int mi = 0; mi < 4; ++mi)
#pragma unroll
            for (int ni = 0; ni < 4; ++ni)
#pragma unroll
                for (int q = 0; q < 4; ++q)
                    sum[mi][ni][q] += acc[mi][ni][q];

        __syncthreads();
    }

    // ---- epilogue: descale -> SMEM cur tile [128 t][132], LIF + ballot ----
    float* cur = (float*)sm;
#pragma unroll
    for (int mi = 0; mi < 4; ++mi)
#pragma unroll
        for (int ni = 0; ni < 4; ++ni) {
            const int r = wm * 64 + mi * 16 + g;
            const int c = wn * 32 + ni * 8 + tg * 2;
            cur[r * 132 + c]           = sum[mi][ni][0] * W_INV;
            cur[r * 132 + c + 1]       = sum[mi][ni][1] * W_INV;
            cur[(r + 8) * 132 + c]     = sum[mi][ni][2] * W_INV;
            cur[(r + 8) * 132 + c + 1] = sum[mi][ni][3] * W_INV;
        }
    __syncthreads();

    if (tid < 128) {
        float mem1 = 0.f;
        uint32_t* dst = g_spkbits + (size_t)b * 128 * 32 + blockIdx.x * 4 + wid;
        float c = cur[tid];
#pragma unroll 4
        for (int t = 0; t < T_STEPS; ++t) {
            float cn = (t + 1 < T_STEPS) ? cur[(t + 1) * 132 + tid] : 0.f;
            const float reset = (mem1 > 1.0f) ? 1.0f : 0.0f;
            mem1 = 0.95f * mem1 + c - reset;
            const uint32_t word = __ballot_sync(0xffffffffu, mem1 > 1.0f);
            if (lane == 0) dst[(size_t)t * 32] = word;
            c = cn;
        }
    }
}

// ===================== K2: cur2 = spk @ W2^T from bitmask ==================
// 32 rows per CTA (grid 1024): W2 SMEM fill amortized 4x vs 8 rows/CTA.
__global__ __launch_bounds__(256)
void snn_gemm2(const float* __restrict__ W2)   // [N_OUT, N_HID]
{
    __shared__ float w2s[N_HID * 11 + 32];
    const int tid  = threadIdx.x;
    const int wid  = tid >> 5;
    const int lane = tid & 31;

    for (int i = tid; i < N_HID * N_OUT; i += 256) {
        const int h = i / N_OUT;
        const int o = i - h * N_OUT;
        w2s[h * 11 + (h >> 5) + o] = W2[o * N_HID + h];
    }
    __syncthreads();

    const int lbase = lane * 353;   // lane*32*11 + lane

#pragma unroll
    for (int r = 0; r < 4; ++r) {
        const size_t m = (size_t)blockIdx.x * 32 + wid * 4 + r;
        uint32_t word = g_spkbits[m * 32 + lane];

        float acc[N_OUT];
#pragma unroll
        for (int o = 0; o < N_OUT; o++) acc[o] = 0.f;

        while (word) {
            const int bit = __ffs(word) - 1;
            word &= word - 1;
            const float* w = w2s + lbase + bit * 11;
#pragma unroll
            for (int o = 0; o < N_OUT; o++) acc[o] += w[o];
        }

#pragma unroll
        for (int o = 0; o < N_OUT; o++) {
            acc[o] += __shfl_down_sync(0xffffffffu, acc[o], 16);
            acc[o] += __shfl_down_sync(0xffffffffu, acc[o], 8);
            acc[o] += __shfl_down_sync(0xffffffffu, acc[o], 4);
            acc[o] += __shfl_down_sync(0xffffffffu, acc[o], 2);
            acc[o] += __shfl_down_sync(0xffffffffu, acc[o], 1);
        }
        if (lane == 0) {
#pragma unroll
            for (int o = 0; o < N_OUT; o++) g_cur2[m * N_OUT + o] = acc[o];
        }
    }
}

// ===================== K3: mem2 leaky integration ==========================
__global__ void snn_scan2(float* __restrict__ out)   // [T, B, N_OUT]
{
    const int id = blockIdx.x * 256 + threadIdx.x;
    if (id >= BATCH * N_OUT) return;
    const int bb = id / N_OUT;
    const int o  = id - bb * N_OUT;

    float m2 = 0.f;
    for (int t = 0; t < T_STEPS; ++t) {
        m2 = 0.95f * m2 + g_cur2[((size_t)bb * T_STEPS + t) * N_OUT + o];
        out[((size_t)t * BATCH + bb) * N_OUT + o] = m2;
    }
}

// ===================== launch ==============================================
extern "C" void kernel_launch(void* const* d_in, const int* in_sizes, int n_in,
                              void* d_out, int out_size)
{
    const float* x  = (const float*)d_in[0];
    const float* W1 = (const float*)d_in[1];
    const float* W2 = (const float*)d_in[2];
    float* out = (float*)d_out;

    cudaFuncSetAttribute(snn_gemm_spike,
                         cudaFuncAttributeMaxDynamicSharedMemorySize, GEMM_SMEM);

    __half* xs; __half* ws;
    cudaGetSymbolAddress((void**)&xs, g_xs);
    cudaGetSymbolAddress((void**)&ws, g_ws);

    {   // fp16 planar split prepass (W1 scaled by 32)
        const size_t nx = (size_t)M_TOTAL * (K_PAD / 4);
        const size_t nw = (size_t)N_HID * (K_PAD / 4);
        split_prepass<<<(unsigned)((nx + 255) / 256), 256>>>(
            x, xs, xs + (size_t)M_TOTAL * K_PAD, M_TOTAL, 1.0f);
        split_prepass<<<(unsigned)((nw + 255) / 256), 256>>>(
            W1, ws, ws + (size_t)N_HID * K_PAD, N_HID, W_SCALE);
    }

    dim3 grid1(N_HID / 128, M_TOTAL / 128);    // (8, 256)
    snn_gemm_spike<<<grid1, 256, GEMM_SMEM>>>();
    snn_gemm2<<<M_TOTAL / 32, 256>>>(W2);
    snn_scan2<<<(BATCH * N_OUT + 255) / 256, 256>>>(out);
}

// round 17
// speedup vs baseline: 1.0825x; 1.0180x over previous
#include <cuda_runtime.h>
#include <cuda_fp16.h>
#include <cstdint>

// ---------------------------------------------------------------------------
// SNN on B200 (compute_100 => mma.sync m16n8k16 FP16, 3-term split [R15 K1],
//              planar planes (W1 x32), ldmatrix feeds, 2-stage ring,
//              merged K2+K3: one CTA per batch element)
// ---------------------------------------------------------------------------

#define BATCH   256
#define T_STEPS 128
#define K_IN    1156
#define N_HID   1024
#define N_OUT   10
#define M_TOTAL (BATCH * T_STEPS)   // 32768
#define KTILES  19                  // ceil(1156/64)
#define K_PAD   (KTILES * 64)       // 1216
#define SROW_W  36                  // SMEM row stride in b32 words
#define PLANE_W (128 * SROW_W)      // 4608 words per plane per stage
#define W_SCALE 32.0f
#define W_INV   0.03125f

__device__ __half   g_xs[(size_t)2 * M_TOTAL * K_PAD];   // hi plane, lo plane
__device__ __half   g_ws[(size_t)2 * N_HID  * K_PAD];    // scaled by 32
__device__ uint32_t g_spkbits[(size_t)M_TOTAL * 32];     // 4 MB

// ===================== helpers =============================================
__device__ __forceinline__ uint32_t smem_u32(const void* p) {
    uint32_t a;
    asm("{ .reg .u64 t; cvta.to.shared.u64 t, %1; cvt.u32.u64 %0, t; }"
        : "=r"(a) : "l"(p));
    return a;
}
__device__ __forceinline__ void cp_async16(uint32_t dst, const void* src) {
    asm volatile("cp.async.cg.shared.global [%0], [%1], 16;"
                 :: "r"(dst), "l"(src));
}
#define CP_COMMIT() asm volatile("cp.async.commit_group;" ::: "memory")
#define CP_WAIT1()  asm volatile("cp.async.wait_group 1;" ::: "memory")

__device__ __forceinline__ void ldsm_x4(uint32_t& r0, uint32_t& r1,
                                        uint32_t& r2, uint32_t& r3, uint32_t addr) {
    asm volatile("ldmatrix.sync.aligned.m8n8.x4.shared.b16 {%0,%1,%2,%3}, [%4];"
                 : "=r"(r0), "=r"(r1), "=r"(r2), "=r"(r3) : "r"(addr));
}

__device__ __forceinline__ void mma16(float* c, const uint32_t* a, const uint32_t* b) {
    asm volatile(
        "mma.sync.aligned.m16n8k16.row.col.f32.f16.f16.f32 "
        "{%0,%1,%2,%3}, {%4,%5,%6,%7}, {%8,%9}, {%0,%1,%2,%3};"
        : "+f"(c[0]), "+f"(c[1]), "+f"(c[2]), "+f"(c[3])
        : "r"(a[0]), "r"(a[1]), "r"(a[2]), "r"(a[3]), "r"(b[0]), "r"(b[1]));
}

// ===================== P: fp16 planar split prepass ========================
__global__ __launch_bounds__(256)
void split_prepass(const float* __restrict__ src, __half* __restrict__ dst_hi,
                   __half* __restrict__ dst_lo, int rows, float scale)
{
    const size_t idx = (size_t)blockIdx.x * 256 + threadIdx.x;  // 4-elem chunk
    const size_t nchunk = (size_t)rows * (K_PAD / 4);
    if (idx >= nchunk) return;
    const int row = (int)(idx / (K_PAD / 4));
    const int k0  = (int)(idx % (K_PAD / 4)) * 4;

    float4 v = make_float4(0.f, 0.f, 0.f, 0.f);
    if (k0 < K_IN) {   // K_IN % 4 == 0
        v = *(const float4*)(src + (size_t)row * K_IN + k0);
        v.x *= scale; v.y *= scale; v.z *= scale; v.w *= scale;
    }

    __half hx = __float2half_rn(v.x), hy = __float2half_rn(v.y);
    __half hz = __float2half_rn(v.z), hw = __float2half_rn(v.w);
    __half lx = __float2half_rn(v.x - __half2float(hx));
    __half ly = __float2half_rn(v.y - __half2float(hy));
    __half lz = __float2half_rn(v.z - __half2float(hz));
    __half lw = __float2half_rn(v.w - __half2float(hw));

    const size_t o = (size_t)row * K_PAD + k0;
    uint2 ph, pl;
    ph.x = (uint32_t)__half_as_ushort(hx) | ((uint32_t)__half_as_ushort(hy) << 16);
    ph.y = (uint32_t)__half_as_ushort(hz) | ((uint32_t)__half_as_ushort(hw) << 16);
    pl.x = (uint32_t)__half_as_ushort(lx) | ((uint32_t)__half_as_ushort(ly) << 16);
    pl.y = (uint32_t)__half_as_ushort(lz) | ((uint32_t)__half_as_ushort(lw) << 16);
    *(uint2*)(dst_hi + o) = ph;
    *(uint2*)(dst_lo + o) = pl;
}

// ===================== K1: GEMM + fused spike scan (R15/R13 config) ========
#define STAGE_W   (4 * PLANE_W)              // 18432 words
#define GEMM_SMEM (2 * STAGE_W * 4)          // 147456 B

__global__ __launch_bounds__(256, 1)
void snn_gemm_spike()
{
    extern __shared__ uint32_t sm[];
    const uint32_t sbase = smem_u32(sm);
    const int tid  = threadIdx.x;          // 256 threads, 8 warps
    const int wid  = tid >> 5;
    const int lane = tid & 31;
    const int wm   = wid >> 2;             // 0..1 -> 64 rows
    const int wn   = wid & 3;              // 0..3 -> 32 cols
    const int b    = blockIdx.y;
    const int n0   = blockIdx.x * 128;

    const __half* xs_hi = g_xs;
    const __half* xs_lo = g_xs + (size_t)M_TOTAL * K_PAD;
    const __half* ws_hi = g_ws;
    const __half* ws_lo = g_ws + (size_t)N_HID * K_PAD;

    const size_t arow0 = (size_t)b * 128 * K_PAD;
    const size_t brow0 = (size_t)n0 * K_PAD;

    const int a_row = wm * 64 + (lane & 7) + ((lane >> 3) & 1) * 8;
    const uint32_t aoff = (uint32_t)(a_row * SROW_W + ((lane >> 4) & 1) * 4) * 4;
    const int b_row = wn * 32 + (lane & 7) + ((lane >> 4) & 1) * 8;
    const uint32_t boff = (uint32_t)(b_row * SROW_W + ((lane >> 3) & 1) * 4) * 4;

    float sum[4][4][4];
#pragma unroll
    for (int i = 0; i < 4; i++)
#pragma unroll
        for (int j = 0; j < 4; j++)
#pragma unroll
            for (int q = 0; q < 4; q++) sum[i][j][q] = 0.f;

    auto prefetch = [&](int it) {
        const int s  = it & 1;
        const int kb = it * 64;
        const uint32_t sst = sbase + (uint32_t)s * STAGE_W * 4;
#pragma unroll
        for (int q = 0; q < 16; ++q) {
            const int plane = q >> 2;
            const int f     = (q & 3) * 256 + tid;
            const int row   = f >> 3;
            const int j     = f & 7;
            const uint32_t soff = (uint32_t)(plane * PLANE_W + row * SROW_W + j * 4) * 4;
            const __half* src;
            if (plane == 0)      src = xs_hi + arow0 + (size_t)row * K_PAD + kb + j * 8;
            else if (plane == 1) src = xs_lo + arow0 + (size_t)row * K_PAD + kb + j * 8;
            else if (plane == 2) src = ws_hi + brow0 + (size_t)row * K_PAD + kb + j * 8;
            else                 src = ws_lo + brow0 + (size_t)row * K_PAD + kb + j * 8;
            cp_async16(sst + soff, src);
        }
    };

    prefetch(0);
    CP_COMMIT();

    const int g  = lane >> 2;
    const int tg = lane & 3;

    for (int it = 0; it < KTILES; ++it) {
        if (it + 1 < KTILES) prefetch(it + 1);
        CP_COMMIT();
        CP_WAIT1();
        __syncthreads();

        const uint32_t stg = sbase + (uint32_t)(it & 1) * STAGE_W * 4;
        const uint32_t aAh = stg + aoff;
        const uint32_t aAl = aAh + PLANE_W * 4;
        const uint32_t bBh = stg + 2 * PLANE_W * 4 + boff;
        const uint32_t bBl = bBh + PLANE_W * 4;

        float acc[4][4][4];
#pragma unroll
        for (int i = 0; i < 4; i++)
#pragma unroll
            for (int j = 0; j < 4; j++)
#pragma unroll
                for (int q = 0; q < 4; q++) acc[i][j][q] = 0.f;

#pragma unroll
        for (int ks = 0; ks < 4; ++ks) {
            uint32_t ahi[4][4], alo[4][4], bhi[4][2], blo[4][2];
            const uint32_t kso = (uint32_t)ks * 32;
#pragma unroll
            for (int mi = 0; mi < 4; ++mi) {
                const uint32_t d = kso + (uint32_t)mi * (16 * SROW_W * 4);
                ldsm_x4(ahi[mi][0], ahi[mi][1], ahi[mi][2], ahi[mi][3], aAh + d);
                ldsm_x4(alo[mi][0], alo[mi][1], alo[mi][2], alo[mi][3], aAl + d);
            }
#pragma unroll
            for (int np = 0; np < 2; ++np) {
                const uint32_t d = kso + (uint32_t)np * (16 * SROW_W * 4);
                ldsm_x4(bhi[2*np][0], bhi[2*np][1], bhi[2*np+1][0], bhi[2*np+1][1], bBh + d);
                ldsm_x4(blo[2*np][0], blo[2*np][1], blo[2*np+1][0], blo[2*np+1][1], bBl + d);
            }
#pragma unroll
            for (int mi = 0; mi < 4; ++mi)
#pragma unroll
                for (int ni = 0; ni < 4; ++ni) {
                    mma16(acc[mi][ni], ahi[mi], bhi[ni]);
                    mma16(acc[mi][ni], ahi[mi], blo[ni]);
                    mma16(acc[mi][ni], alo[mi], bhi[ni]);
                }
        }

#pragma unroll
        for (int mi = 0; mi < 4; ++mi)
#pragma unroll
            for (int ni = 0; ni < 4; ++ni)
#pragma unroll
                for (int q = 0; q < 4; ++q)
                    sum[mi][ni][q] += acc[mi][ni][q];

        __syncthreads();
    }

    // ---- epilogue: descale -> SMEM cur tile [128 t][132], LIF + ballot ----
    float* cur = (float*)sm;
#pragma unroll
    for (int mi = 0; mi < 4; ++mi)
#pragma unroll
        for (int ni = 0; ni < 4; ++ni) {
            const int r = wm * 64 + mi * 16 + g;
            const int c = wn * 32 + ni * 8 + tg * 2;
            cur[r * 132 + c]           = sum[mi][ni][0] * W_INV;
            cur[r * 132 + c + 1]       = sum[mi][ni][1] * W_INV;
            cur[(r + 8) * 132 + c]     = sum[mi][ni][2] * W_INV;
            cur[(r + 8) * 132 + c + 1] = sum[mi][ni][3] * W_INV;
        }
    __syncthreads();

    if (tid < 128) {
        float mem1 = 0.f;
        uint32_t* dst = g_spkbits + (size_t)b * 128 * 32 + blockIdx.x * 4 + wid;
        float c = cur[tid];
#pragma unroll 4
        for (int t = 0; t < T_STEPS; ++t) {
            float cn = (t + 1 < T_STEPS) ? cur[(t + 1) * 132 + tid] : 0.f;
            const float reset = (mem1 > 1.0f) ? 1.0f : 0.0f;
            mem1 = 0.95f * mem1 + c - reset;
            const uint32_t word = __ballot_sync(0xffffffffu, mem1 > 1.0f);
            if (lane == 0) dst[(size_t)t * 32] = word;
            c = cn;
        }
    }
}

// ===================== K2+K3 merged: spk @ W2^T + mem2 scan ================
// One CTA per batch element b: 8 warps x 16 t-rows; cur2 kept in SMEM;
// mem2 leaky integration runs in-kernel (no g_cur2 round trip, no K3).
// Dynamic SMEM: w2s [N_HID*11+32] floats, c2 [128*10] floats.
#define W2S_FLOATS (N_HID * 11 + 32)               // 11296
#define OUT_SMEM   ((W2S_FLOATS + T_STEPS * N_OUT) * 4)   // 50304 B

__global__ __launch_bounds__(256)
void snn_out(const float* __restrict__ W2,   // [N_OUT, N_HID]
             float* __restrict__ out)        // [T, B, N_OUT]
{
    extern __shared__ float dsm[];
    float* w2s = dsm;
    float* c2  = dsm + W2S_FLOATS;          // [t][o]
    const int tid  = threadIdx.x;
    const int wid  = tid >> 5;
    const int lane = tid & 31;
    const int b    = blockIdx.x;

    for (int i = tid; i < N_HID * N_OUT; i += 256) {
        const int h = i / N_OUT;
        const int o = i - h * N_OUT;
        w2s[h * 11 + (h >> 5) + o] = W2[o * N_HID + h];
    }
    __syncthreads();

    const int lbase = lane * 353;   // lane*32*11 + lane

#pragma unroll
    for (int r = 0; r < 16; ++r) {
        const int t = wid * 16 + r;
        const size_t m = (size_t)b * T_STEPS + t;
        uint32_t word = g_spkbits[m * 32 + lane];

        float acc[N_OUT];
#pragma unroll
        for (int o = 0; o < N_OUT; o++) acc[o] = 0.f;

        while (word) {
            const int bit = __ffs(word) - 1;
            word &= word - 1;
            const float* w = w2s + lbase + bit * 11;
#pragma unroll
            for (int o = 0; o < N_OUT; o++) acc[o] += w[o];
        }

#pragma unroll
        for (int o = 0; o < N_OUT; o++) {
            acc[o] += __shfl_down_sync(0xffffffffu, acc[o], 16);
            acc[o] += __shfl_down_sync(0xffffffffu, acc[o], 8);
            acc[o] += __shfl_down_sync(0xffffffffu, acc[o], 4);
            acc[o] += __shfl_down_sync(0xffffffffu, acc[o], 2);
            acc[o] += __shfl_down_sync(0xffffffffu, acc[o], 1);
        }
        if (lane == 0) {
#pragma unroll
            for (int o = 0; o < N_OUT; o++) c2[t * N_OUT + o] = acc[o];
        }
    }
    __syncthreads();

    if (tid < N_OUT) {
        float m2 = 0.f;
        for (int t = 0; t < T_STEPS; ++t) {
            m2 = 0.95f * m2 + c2[t * N_OUT + tid];
            out[((size_t)t * BATCH + b) * N_OUT + tid] = m2;
        }
    }
}

// ===================== launch ==============================================
extern "C" void kernel_launch(void* const* d_in, const int* in_sizes, int n_in,
                              void* d_out, int out_size)
{
    const float* x  = (const float*)d_in[0];
    const float* W1 = (const float*)d_in[1];
    const float* W2 = (const float*)d_in[2];
    float* out = (float*)d_out;

    cudaFuncSetAttribute(snn_gemm_spike,
                         cudaFuncAttributeMaxDynamicSharedMemorySize, GEMM_SMEM);
    cudaFuncSetAttribute(snn_out,
                         cudaFuncAttributeMaxDynamicSharedMemorySize, OUT_SMEM);

    __half* xs; __half* ws;
    cudaGetSymbolAddress((void**)&xs, g_xs);
    cudaGetSymbolAddress((void**)&ws, g_ws);

    {   // fp16 planar split prepass (W1 scaled by 32)
        const size_t nx = (size_t)M_TOTAL * (K_PAD / 4);
        const size_t nw = (size_t)N_HID * (K_PAD / 4);
        split_prepass<<<(unsigned)((nx + 255) / 256), 256>>>(
            x, xs, xs + (size_t)M_TOTAL * K_PAD, M_TOTAL, 1.0f);
        split_prepass<<<(unsigned)((nw + 255) / 256), 256>>>(
            W1, ws, ws + (size_t)N_HID * K_PAD, N_HID, W_SCALE);
    }

    dim3 grid1(N_HID / 128, M_TOTAL / 128);    // (8, 256)
    snn_gemm_spike<<<grid1, 256, GEMM_SMEM>>>();
    snn_out<<<BATCH, 256, OUT_SMEM>>>(W2, out);
}